// round 10
// baseline (speedup 1.0000x reference)
#include <cuda_runtime.h>
#include <cuda_bf16.h>
#include <cstdint>

#define B_   8
#define C_   128
#define MID_ 64
#define OUT_ 128
#define TN_  2048
#define QT_  16

typedef unsigned long long ull;

// ---- f32x2 packed-FMA helpers ----
__device__ __forceinline__ void fma2(ull &d, ull a, ull b) {
    asm("fma.rn.f32x2 %0, %1, %2, %0;" : "+l"(d) : "l"(a), "l"(b));
}
__device__ __forceinline__ ull bcast2(float x) {
    ull r; asm("mov.b64 %0, {%1, %1};" : "=l"(r) : "f"(x)); return r;
}
__device__ __forceinline__ float2 unpk(ull v) {
    float2 f; asm("mov.b64 {%0, %1}, %2;" : "=f"(f.x), "=f"(f.y) : "l"(v)); return f;
}

// ---- warp MMA helpers (baseline sm_80+ features; compile for sm_103) ----
__device__ __forceinline__ uint32_t smem_u32(const void* p) {
    uint32_t a;
    asm("{ .reg .u64 t; cvta.to.shared.u64 t, %1; cvt.u32.u64 %0, t; }" : "=r"(a) : "l"(p));
    return a;
}
__device__ __forceinline__ void ldm_x4(uint32_t* r, uint32_t addr) {
    asm volatile("ldmatrix.sync.aligned.m8n8.x4.shared.b16 {%0,%1,%2,%3}, [%4];"
        : "=r"(r[0]), "=r"(r[1]), "=r"(r[2]), "=r"(r[3]) : "r"(addr));
}
__device__ __forceinline__ void ldm_x2(uint32_t* r, uint32_t addr) {
    asm volatile("ldmatrix.sync.aligned.m8n8.x2.shared.b16 {%0,%1}, [%2];"
        : "=r"(r[0]), "=r"(r[1]) : "r"(addr));
}
__device__ __forceinline__ void mma_bf16(float* d, const uint32_t* a, const uint32_t* b) {
    asm volatile(
        "mma.sync.aligned.m16n8k16.row.col.f32.bf16.bf16.f32 "
        "{%0,%1,%2,%3}, {%4,%5,%6,%7}, {%8,%9}, {%0,%1,%2,%3};"
        : "+f"(d[0]), "+f"(d[1]), "+f"(d[2]), "+f"(d[3])
        : "r"(a[0]), "r"(a[1]), "r"(a[2]), "r"(a[3]), "r"(b[0]), "r"(b[1]));
}

__device__ __forceinline__ unsigned pk2(__nv_bfloat16 a, __nv_bfloat16 b) {
    __nv_bfloat162 t = __halves2bfloat162(a, b);
    return *reinterpret_cast<unsigned*>(&t);
}
// split 4 fp32 -> hi/lo bf16 uint2 pairs
__device__ __forceinline__ void split4(float4 v, uint2& hi, uint2& lo) {
    __nv_bfloat16 h0 = __float2bfloat16(v.x), h1 = __float2bfloat16(v.y);
    __nv_bfloat16 h2 = __float2bfloat16(v.z), h3 = __float2bfloat16(v.w);
    float l0 = v.x - __bfloat162float(h0), l1 = v.y - __bfloat162float(h1);
    float l2 = v.z - __bfloat162float(h2), l3 = v.w - __bfloat162float(h3);
    hi = make_uint2(pk2(h0, h1), pk2(h2, h3));
    lo = make_uint2(pk2(__float2bfloat16(l0), __float2bfloat16(l1)),
                    pk2(__float2bfloat16(l2), __float2bfloat16(l3)));
}

// ---- scratch globals ----
__device__ __align__(16) __nv_bfloat16 g_thT_hi[B_*TN_*MID_];  // theta^T [b][q][m]
__device__ __align__(16) __nv_bfloat16 g_thT_lo[B_*TN_*MID_];
__device__ __align__(16) __nv_bfloat16 g_phT_hi[B_*TN_*MID_];  // phi^T  [b][k][m]
__device__ __align__(16) __nv_bfloat16 g_phT_lo[B_*TN_*MID_];
__device__ __align__(16) float g_gp  [B_*MID_*TN_];            // g proj fp32 [b][m][k]
__device__ __align__(16) __nv_bfloat16 g_Eh[(size_t)B_*TN_*TN_];  // exp(S) hi [b][q][k]
__device__ __align__(16) __nv_bfloat16 g_El[(size_t)B_*TN_*TN_];  // exp(S) lo
__device__ __align__(16) float g_part[B_*QT_*TN_];
__device__ __align__(16) float g_invl[B_*TN_];
__device__ __align__(16) float g_ref [B_*OUT_*TN_];

// ============================================================
// Kernel 1: fused projections; theta/phi -> bf16 hi/lo transposed, g -> fp32
// grid (16 qt, 8 b, 3 proj), 256 threads
// ============================================================
__global__ __launch_bounds__(256) void proj_kernel(
    const float* __restrict__ pc,
    const float* __restrict__ tw, const float* __restrict__ tb,
    const float* __restrict__ pw, const float* __restrict__ pb,
    const float* __restrict__ gw, const float* __restrict__ gb)
{
    extern __shared__ float sm[];
    float* Ws = sm;            // [c][m]
    float* Ps = sm + C_*MID_;  // [c][q]
    int tid = threadIdx.x;
    int qt = blockIdx.x, b = blockIdx.y, z = blockIdx.z;
    const float* w    = (z==0) ? tw : (z==1) ? pw : gw;
    const float* bias = (z==0) ? tb : (z==1) ? pb : gb;
    int q0 = qt*128;

    for (int idx = tid; idx < C_*MID_; idx += 256) {
        int m = idx >> 7, c = idx & 127;
        Ws[c*MID_ + m] = w[m*C_ + c];
    }
    {
        const float4* pcb = (const float4*)(pc + ((size_t)b*C_)*TN_ + q0);
        float4* Ps4 = (float4*)Ps;
        for (int idx = tid; idx < C_*32; idx += 256) {
            int c = idx >> 5, q4 = idx & 31;
            Ps4[c*32 + q4] = pcb[(size_t)c*(TN_/4) + q4];
        }
    }
    __syncthreads();

    int ty = tid >> 4, tx = tid & 15;
    int m0 = ty*4, ql = tx*8;
    ull accp[4][4];
    #pragma unroll
    for (int i = 0; i < 4; i++)
        #pragma unroll
        for (int j = 0; j < 4; j++) accp[i][j] = 0ull;

    for (int c = 0; c < C_; c++) {
        float4 wv = *(const float4*)&Ws[c*MID_ + m0];
        ull wb[4] = {bcast2(wv.x), bcast2(wv.y), bcast2(wv.z), bcast2(wv.w)};
        const ulonglong2* p128 = (const ulonglong2*)&Ps[c*128 + ql];
        ulonglong2 P0 = p128[0], P1 = p128[1];
        ull pp[4] = {P0.x, P0.y, P1.x, P1.y};
        #pragma unroll
        for (int i = 0; i < 4; i++)
            #pragma unroll
            for (int j = 0; j < 4; j++) fma2(accp[i][j], wb[i], pp[j]);
    }

    float v[4][8];
    #pragma unroll
    for (int i = 0; i < 4; i++) {
        float bv = bias[m0 + i];
        #pragma unroll
        for (int j = 0; j < 4; j++) {
            float2 u = unpk(accp[i][j]);
            v[i][2*j]   = fmaxf(u.x + bv, 0.f);
            v[i][2*j+1] = fmaxf(u.y + bv, 0.f);
        }
    }

    if (z == 2) {
        float* ob = g_gp + ((size_t)b*MID_)*TN_ + q0 + ql;
        #pragma unroll
        for (int i = 0; i < 4; i++) {
            *(float4*)&ob[(size_t)(m0+i)*TN_]     = make_float4(v[i][0], v[i][1], v[i][2], v[i][3]);
            *(float4*)&ob[(size_t)(m0+i)*TN_ + 4] = make_float4(v[i][4], v[i][5], v[i][6], v[i][7]);
        }
    } else {
        __nv_bfloat16* dh = z ? g_phT_hi : g_thT_hi;
        __nv_bfloat16* dl = z ? g_phT_lo : g_thT_lo;
        #pragma unroll
        for (int j = 0; j < 8; j++) {
            int q = q0 + ql + j;
            size_t base = (size_t)(b*TN_ + q)*MID_ + m0;
            uint2 hi, lo;
            split4(make_float4(v[0][j], v[1][j], v[2][j], v[3][j]), hi, lo);
            *(uint2*)(dh + base) = hi;
            *(uint2*)(dl + base) = lo;
        }
    }
}

// ============================================================
// Kernel 2: HMMA score tile: S = theta^T phi (bf16 3-term), exp,
//           E hi/lo bf16 [b][q][k] + per-qt column partial sums.
// grid (16 kt, 16 qt, 8 b), 256 threads (8 warps: 4 q-blocks x 2 k-blocks)
// ============================================================
#define SROW 144          // padded row bytes (72 bf16)
#define S_AH 0
#define S_AL 18432
#define S_BH 36864
#define S_BL 55296
#define S_SMEM 73728      // Esm fp32 [128][132] = 67584 reuses [0..)

__global__ __launch_bounds__(256) void score_mma()
{
    extern __shared__ __align__(16) char smc[];
    uint32_t sb = smem_u32(smc);
    int tid = threadIdx.x, wid = tid >> 5, lane = tid & 31;
    int kt = blockIdx.x, qt = blockIdx.y, b = blockIdx.z;
    int q0 = qt*128, k0 = kt*128;

    // load 4 tiles: theta/phi hi/lo, 128 rows x 64 bf16 (128B), padded rows
    {
        const uint4* Ah = (const uint4*)(g_thT_hi + (size_t)(b*TN_ + q0)*MID_);
        const uint4* Al = (const uint4*)(g_thT_lo + (size_t)(b*TN_ + q0)*MID_);
        const uint4* Bh = (const uint4*)(g_phT_hi + (size_t)(b*TN_ + k0)*MID_);
        const uint4* Bl = (const uint4*)(g_phT_lo + (size_t)(b*TN_ + k0)*MID_);
        for (int idx = tid; idx < 1024; idx += 256) {
            int row = idx >> 3, u = idx & 7;
            int off = row*SROW + u*16;
            *(uint4*)(smc + S_AH + off) = Ah[idx];
            *(uint4*)(smc + S_AL + off) = Al[idx];
            *(uint4*)(smc + S_BH + off) = Bh[idx];
            *(uint4*)(smc + S_BL + off) = Bl[idx];
        }
    }
    __syncthreads();

    int qb = (wid & 3)*32, kb = (wid >> 2)*64;
    float d[2][8][4];
    #pragma unroll
    for (int i = 0; i < 2; i++)
        #pragma unroll
        for (int j = 0; j < 8; j++)
            #pragma unroll
            for (int r = 0; r < 4; r++) d[i][j][r] = 0.f;

    const int aoff[3] = {S_AH, S_AH, S_AL};
    const int boff[3] = {S_BH, S_BL, S_BH};
    #pragma unroll
    for (int s = 0; s < 3; s++) {
        #pragma unroll
        for (int ks = 0; ks < 4; ks++) {
            uint32_t a[2][4];
            #pragma unroll
            for (int i = 0; i < 2; i++)
                ldm_x4(a[i], sb + aoff[s] + (qb + i*16 + (lane & 15))*SROW
                            + (ks*16 + (lane >> 4)*8)*2);
            #pragma unroll
            for (int j = 0; j < 8; j++) {
                uint32_t bfr[2];
                ldm_x2(bfr, sb + boff[s] + (kb + j*8 + (lane & 7))*SROW
                           + (ks*16 + ((lane >> 3) & 1)*8)*2);
                mma_bf16(d[0][j], a[0], bfr);
                mma_bf16(d[1][j], a[1], bfr);
            }
        }
    }

    __syncthreads();   // operand tiles dead; reuse smem for Esm
    float* Esm = (float*)smc;   // [q][132]
    int r0 = qb + (lane >> 2), c0 = kb + (lane & 3)*2;
    #pragma unroll
    for (int i = 0; i < 2; i++)
        #pragma unroll
        for (int j = 0; j < 8; j++) {
            int r = r0 + i*16, c = c0 + j*8;
            *(float2*)&Esm[r*132 + c]       = make_float2(__expf(d[i][j][0]), __expf(d[i][j][1]));
            *(float2*)&Esm[(r + 8)*132 + c] = make_float2(__expf(d[i][j][2]), __expf(d[i][j][3]));
        }
    __syncthreads();

    // deterministic column partial sums over this q-tile
    if (tid < 128) {
        float s = 0.f;
        for (int qq = 0; qq < 128; qq++) s += Esm[qq*132 + tid];
        g_part[((size_t)b*QT_ + qt)*TN_ + k0 + tid] = s;
    }
    // store E hi/lo bf16, coalesced
    {
        uint4* Eh4 = (uint4*)g_Eh;
        uint4* El4 = (uint4*)g_El;
        for (int idx = tid; idx < 2048; idx += 256) {
            int q = idx >> 4, u = idx & 15;
            float4 va = *(float4*)&Esm[q*132 + u*8];
            float4 vb = *(float4*)&Esm[q*132 + u*8 + 4];
            uint2 ha, la, hb, lb;
            split4(va, ha, la); split4(vb, hb, lb);
            size_t go = ((size_t)(b*TN_ + q0 + q)*TN_ + k0)/8 + u;
            Eh4[go] = make_uint4(ha.x, ha.y, hb.x, hb.y);
            El4[go] = make_uint4(la.x, la.y, lb.x, lb.y);
        }
    }
}

// ============================================================
// Kernel 2b: reduce partials -> 1/l[b][k]
// ============================================================
__global__ __launch_bounds__(256) void lsum_kernel()
{
    int i = blockIdx.x*256 + threadIdx.x;
    int b = i >> 11, k = i & (TN_ - 1);
    float s = 0.f;
    #pragma unroll
    for (int t = 0; t < QT_; t++) s += g_part[((size_t)b*QT_ + t)*TN_ + k];
    g_invl[(size_t)b*TN_ + k] = 1.f / s;
}

// ============================================================
// Kernel 3: HMMA Y GEMM over full k (32 chunks of 64) + fused refine.
// Y[q][m] = sum_k E[q][k]*(G[m][k]/l[k]);  ref = relu(RW@Y^T + rb)
// grid (16 qt, 8 b), 256 threads
// ============================================================
#define Y_EH  0
#define Y_EL  18432
#define Y_GH  36864        // 64 rows * 144B
#define Y_GL  46080
#define Y_INV 55296        // fp32[2048]
#define Y_YS  0            // phase2: Ys fp32 [64 m][132 q] = 33792B
#define Y_RW  33792        // phase2: RWs fp32 [64][128]    = 32768B
#define Y_SMEM 66560

__global__ __launch_bounds__(256) void y_mma(
    const float* __restrict__ rw, const float* __restrict__ rb)
{
    extern __shared__ __align__(16) char smc[];
    uint32_t sb = smem_u32(smc);
    int tid = threadIdx.x, wid = tid >> 5, lane = tid & 31;
    int qt = blockIdx.x, b = blockIdx.y;
    int q0 = qt*128;

    float* sInv = (float*)(smc + Y_INV);
    for (int idx = tid; idx < TN_; idx += 256)
        sInv[idx] = g_invl[(size_t)b*TN_ + idx];

    int qb = (wid & 3)*32, mb = (wid >> 2)*32;
    float d[2][4][4];
    #pragma unroll
    for (int i = 0; i < 2; i++)
        #pragma unroll
        for (int j = 0; j < 4; j++)
            #pragma unroll
            for (int r = 0; r < 4; r++) d[i][j][r] = 0.f;

    const uint4* Eh4 = (const uint4*)g_Eh;
    const uint4* El4 = (const uint4*)g_El;
    const float4* Gg = (const float4*)(g_gp + (size_t)b*MID_*TN_);

    const int aoff[3] = {Y_EH, Y_EH, Y_EL};
    const int boff[3] = {Y_GH, Y_GL, Y_GH};

    for (int c = 0; c < 32; c++) {
        int kc = c*64;
        __syncthreads();   // previous chunk's mma reads complete
        // E tiles: 128 rows x 64 bf16
        for (int idx = tid; idx < 1024; idx += 256) {
            int row = idx >> 3, u = idx & 7;
            size_t go = ((size_t)(b*TN_ + q0 + row)*TN_ + kc)/8 + u;
            int off = row*SROW + u*16;
            *(uint4*)(smc + Y_EH + off) = Eh4[go];
            *(uint4*)(smc + Y_EL + off) = El4[go];
        }
        // G tiles: 64 rows x 64 fp32 -> scaled hi/lo bf16
        for (int idx = tid; idx < 1024; idx += 256) {
            int m = idx >> 4, u = idx & 15;
            float4 f = Gg[(size_t)m*(TN_/4) + (kc >> 2) + u];
            f.x *= sInv[kc + u*4];     f.y *= sInv[kc + u*4 + 1];
            f.z *= sInv[kc + u*4 + 2]; f.w *= sInv[kc + u*4 + 3];
            uint2 hi, lo;
            split4(f, hi, lo);
            int off = m*SROW + u*8;
            *(uint2*)(smc + Y_GH + off) = hi;
            *(uint2*)(smc + Y_GL + off) = lo;
        }
        __syncthreads();

        #pragma unroll
        for (int s = 0; s < 3; s++) {
            #pragma unroll
            for (int ks = 0; ks < 4; ks++) {
                uint32_t a[2][4];
                #pragma unroll
                for (int i = 0; i < 2; i++)
                    ldm_x4(a[i], sb + aoff[s] + (qb + i*16 + (lane & 15))*SROW
                                + (ks*16 + (lane >> 4)*8)*2);
                #pragma unroll
                for (int j = 0; j < 4; j++) {
                    uint32_t bfr[2];
                    ldm_x2(bfr, sb + boff[s] + (mb + j*8 + (lane & 7))*SROW
                               + (ks*16 + ((lane >> 3) & 1)*8)*2);
                    mma_bf16(d[0][j], a[0], bfr);
                    mma_bf16(d[1][j], a[1], bfr);
                }
            }
        }
    }

    // ---- stage Y transposed: Ys[m][132 + q] (fp32) ----
    __syncthreads();
    float* Ys = (float*)(smc + Y_YS);
    {
        int rq = qb + (lane >> 2), cm = mb + (lane & 3)*2;
        #pragma unroll
        for (int i = 0; i < 2; i++)
            #pragma unroll
            for (int j = 0; j < 4; j++) {
                int m = cm + j*8, q = rq + i*16;
                Ys[m*132 + q]           = d[i][j][0];
                Ys[(m + 1)*132 + q]     = d[i][j][1];
                Ys[m*132 + q + 8]       = d[i][j][2];
                Ys[(m + 1)*132 + q + 8] = d[i][j][3];
            }
    }
    float* RWs = (float*)(smc + Y_RW);
    for (int idx = tid; idx < 64*128; idx += 256) {
        int m = idx & 63, o = idx >> 6;
        RWs[m*128 + o] = rw[o*MID_ + m];
    }
    __syncthreads();

    // ---- fused refine GEMM (f32x2 SIMT; 1 wave, tiny) ----
    int ty = tid >> 4, tx = tid & 15;
    ull accp[4][8];
    #pragma unroll
    for (int i = 0; i < 4; i++)
        #pragma unroll
        for (int j = 0; j < 8; j++) accp[i][j] = 0ull;

    for (int m = 0; m < MID_; m++) {
        const ulonglong2* a128 = (const ulonglong2*)&RWs[m*128 + ty*8];
        ulonglong2 A0 = a128[0], A1 = a128[1];
        ull ap[4] = {A0.x, A0.y, A1.x, A1.y};
        float4 b0 = *(const float4*)&Ys[m*132 + tx*8];
        float4 b1 = *(const float4*)&Ys[m*132 + tx*8 + 4];
        ull bb[8] = {bcast2(b0.x), bcast2(b0.y), bcast2(b0.z), bcast2(b0.w),
                     bcast2(b1.x), bcast2(b1.y), bcast2(b1.z), bcast2(b1.w)};
        #pragma unroll
        for (int i = 0; i < 4; i++)
            #pragma unroll
            for (int j = 0; j < 8; j++) fma2(accp[i][j], ap[i], bb[j]);
    }

    #pragma unroll
    for (int i2 = 0; i2 < 4; i2++) {
        float2 u[8];
        #pragma unroll
        for (int j = 0; j < 8; j++) u[j] = unpk(accp[i2][j]);
        int o0 = ty*8 + 2*i2;
        float bv0 = rb[o0], bv1 = rb[o0 + 1];
        float* r0 = g_ref + ((size_t)b*OUT_ + o0)*TN_ + q0 + tx*8;
        float* r1 = r0 + TN_;
        *(float4*)r0       = make_float4(fmaxf(u[0].x+bv0,0.f), fmaxf(u[1].x+bv0,0.f),
                                         fmaxf(u[2].x+bv0,0.f), fmaxf(u[3].x+bv0,0.f));
        *(float4*)(r0 + 4) = make_float4(fmaxf(u[4].x+bv0,0.f), fmaxf(u[5].x+bv0,0.f),
                                         fmaxf(u[6].x+bv0,0.f), fmaxf(u[7].x+bv0,0.f));
        *(float4*)r1       = make_float4(fmaxf(u[0].y+bv1,0.f), fmaxf(u[1].y+bv1,0.f),
                                         fmaxf(u[2].y+bv1,0.f), fmaxf(u[3].y+bv1,0.f));
        *(float4*)(r1 + 4) = make_float4(fmaxf(u[4].y+bv1,0.f), fmaxf(u[5].y+bv1,0.f),
                                         fmaxf(u[6].y+bv1,0.f), fmaxf(u[7].y+bv1,0.f));
    }
}

// ============================================================
// Kernel 4: raw-reshape permute + residual
// ============================================================
__global__ __launch_bounds__(256) void out_kernel(
    const float* __restrict__ pc, float* __restrict__ out)
{
    extern __shared__ float sm[];   // [128][129]
    int tid = threadIdx.x;
    int ut = blockIdx.x, b = blockIdx.y;
    int u0 = ut*128;
    for (int idx = tid; idx < 128*128; idx += 256) {
        int u = idx >> 7, c = idx & 127;
        int gu = u0 + u;
        int o = gu >> 4;
        int q = ((gu & 15) << 7) | c;
        sm[u*129 + c] = g_ref[((size_t)b*OUT_ + o)*TN_ + q];
    }
    __syncthreads();
    for (int idx = tid; idx < 128*128; idx += 256) {
        int c = idx >> 7, uu = idx & 127;
        size_t p = ((size_t)b*C_ + c)*TN_ + u0 + uu;
        out[p] = sm[uu*129 + c] + pc[p];
    }
}

// ============================================================
extern "C" void kernel_launch(void* const* d_in, const int* in_sizes, int n_in,
                              void* d_out, int out_size)
{
    const float* pc = (const float*)d_in[0];
    const float* tw = (const float*)d_in[1];
    const float* tb = (const float*)d_in[2];
    const float* pw = (const float*)d_in[3];
    const float* pb = (const float*)d_in[4];
    const float* gw = (const float*)d_in[5];
    const float* gb = (const float*)d_in[6];
    const float* rw = (const float*)d_in[7];
    const float* rb = (const float*)d_in[8];
    float* out = (float*)d_out;

    cudaFuncSetAttribute(proj_kernel, cudaFuncAttributeMaxDynamicSharedMemorySize, 98304);
    cudaFuncSetAttribute(score_mma,   cudaFuncAttributeMaxDynamicSharedMemorySize, S_SMEM);
    cudaFuncSetAttribute(y_mma,       cudaFuncAttributeMaxDynamicSharedMemorySize, Y_SMEM);
    cudaFuncSetAttribute(out_kernel,  cudaFuncAttributeMaxDynamicSharedMemorySize, 66048);

    proj_kernel <<<dim3(16, 8, 3),  256, 98304>>>(pc, tw, tb, pw, pb, gw, gb);
    score_mma   <<<dim3(16, 16, 8), 256, S_SMEM>>>();
    lsum_kernel <<<64,              256        >>>();
    y_mma       <<<dim3(16, 8),     256, Y_SMEM>>>(rw, rb);
    out_kernel  <<<dim3(16, 8),     256, 66048>>>(pc, out);
}